// round 3
// baseline (speedup 1.0000x reference)
#include <cuda_runtime.h>
#include <cstdint>

// Problem shape (fixed by reference): B=2, S=2048, D=1024, V=32000
#define M_TOT 4096
#define K_DIM 1024
#define V_TOT 32000

#define BM 128
#define BN 128
#define BK 32
#define NTHREADS 256
#define NCHUNK 50          // V split into 50 chunks
#define TPC 5              // 5 BN-tiles per chunk -> 640 vocab rows per chunk

// Scratch (allocation-free rule: __device__ globals)
__device__ float g_perturbed[M_TOT * K_DIM];        // 16.8 MB
__device__ float g_pmax[M_TOT * NCHUNK];
__device__ int   g_pidx[M_TOT * NCHUNK];

// ---------------- packed f32x2 helpers (Blackwell PTX-only path) -------------
__device__ __forceinline__ unsigned long long fma2(unsigned long long a,
                                                   unsigned long long b,
                                                   unsigned long long c) {
    unsigned long long d;
    asm("fma.rn.f32x2 %0, %1, %2, %3;" : "=l"(d) : "l"(a), "l"(b), "l"(c));
    return d;
}
__device__ __forceinline__ unsigned long long pack2(float lo, float hi) {
    unsigned long long d;
    asm("mov.b64 %0, {%1, %2};" : "=l"(d) : "f"(lo), "f"(hi));
    return d;
}
__device__ __forceinline__ float2 unpack2(unsigned long long v) {
    float2 r;
    asm("mov.b64 {%0, %1}, %2;" : "=f"(r.x), "=f"(r.y) : "l"(v));
    return r;
}

// ---------------- kernel 0: perturbed = embeds + noise -----------------------
__global__ void perturb_kernel(const float* __restrict__ e,
                               const float* __restrict__ n) {
    int i = blockIdx.x * blockDim.x + threadIdx.x;   // one float4 per thread
    float4 a = reinterpret_cast<const float4*>(e)[i];
    float4 b = reinterpret_cast<const float4*>(n)[i];
    a.x += b.x; a.y += b.y; a.z += b.z; a.w += b.w;
    reinterpret_cast<float4*>(g_perturbed)[i] = a;
}

// ---------------- kernel 1: fp32 GEMM (f32x2) + fused running argmax ---------
// grid: (32 m-blocks [fast], 50 v-chunks).  256 threads, 8x8 per thread
// (4+4 split rows/cols for conflict-free vectorized smem reads).
__global__ __launch_bounds__(NTHREADS, 2)
void gemm_argmax_kernel(const float* __restrict__ table) {
    __shared__ __align__(16) float As[BK][BM + 4];   // pad 4: aligned + bank-spread
    __shared__ __align__(16) float Bs[BK][BN + 4];

    const int t  = threadIdx.x;
    const int tx = t & 15;          // column group
    const int ty = t >> 4;          // row group
    const int mBase = blockIdx.x * BM;
    const int chunk = blockIdx.y;

    float bestVal[8];
    int   bestIdx[8];
#pragma unroll
    for (int i = 0; i < 8; ++i) {
        bestVal[i] = __int_as_float(0xff800000);     // -inf
        bestIdx[i] = 0x7fffffff;
    }

    const float* __restrict__ A = g_perturbed;

    for (int vt = 0; vt < TPC; ++vt) {
        const int vBase = (chunk * TPC + vt) * BN;

        unsigned long long acc[8][4];
#pragma unroll
        for (int i = 0; i < 8; ++i)
#pragma unroll
            for (int j = 0; j < 4; ++j) acc[i][j] = 0ull;

        for (int kt = 0; kt < K_DIM / BK; ++kt) {
            const int kBase = kt * BK;
            // cooperative tile load: 4 float4 per matrix per thread, coalesced
#pragma unroll
            for (int i = 0; i < 4; ++i) {
                int f   = t + i * NTHREADS;
                int row = f >> 3;        // 8 float4 per 32-col row
                int c4  = f & 7;
                float4 av = *reinterpret_cast<const float4*>(
                    A + (mBase + row) * K_DIM + kBase + c4 * 4);
                float4 bv = *reinterpret_cast<const float4*>(
                    table + (vBase + row) * K_DIM + kBase + c4 * 4);
                As[c4 * 4 + 0][row] = av.x;
                As[c4 * 4 + 1][row] = av.y;
                As[c4 * 4 + 2][row] = av.z;
                As[c4 * 4 + 3][row] = av.w;
                Bs[c4 * 4 + 0][row] = bv.x;
                Bs[c4 * 4 + 1][row] = bv.y;
                Bs[c4 * 4 + 2][row] = bv.z;
                Bs[c4 * 4 + 3][row] = bv.w;
            }
            __syncthreads();

#pragma unroll
            for (int k = 0; k < BK; ++k) {
                float4 av0 = *reinterpret_cast<const float4*>(&As[k][ty * 4]);
                float4 av1 = *reinterpret_cast<const float4*>(&As[k][64 + ty * 4]);
                // b pairs read directly as packed 64-bit (no re-pack needed)
                ulonglong2 bu0 = *reinterpret_cast<const ulonglong2*>(&Bs[k][tx * 4]);
                ulonglong2 bu1 = *reinterpret_cast<const ulonglong2*>(&Bs[k][64 + tx * 4]);
                unsigned long long B2[4] = {bu0.x, bu0.y, bu1.x, bu1.y};
                float a[8] = {av0.x, av0.y, av0.z, av0.w,
                              av1.x, av1.y, av1.z, av1.w};
#pragma unroll
                for (int i = 0; i < 8; ++i) {
                    unsigned long long A2 = pack2(a[i], a[i]);
#pragma unroll
                    for (int jj = 0; jj < 4; ++jj)
                        acc[i][jj] = fma2(A2, B2[jj], acc[i][jj]);
                }
            }
            __syncthreads();
        }

        // fold this V-tile into the running per-row argmax
#pragma unroll
        for (int i = 0; i < 8; ++i) {
#pragma unroll
            for (int jj = 0; jj < 4; ++jj) {
                float2 v = unpack2(acc[i][jj]);
                int colb = ((jj < 2) ? (tx * 4) : (64 + tx * 4)) + (jj & 1) * 2;
                int g0 = vBase + colb;
                if (v.x > bestVal[i] || (v.x == bestVal[i] && g0 < bestIdx[i])) {
                    bestVal[i] = v.x; bestIdx[i] = g0;
                }
                if (v.y > bestVal[i] || (v.y == bestVal[i] && g0 + 1 < bestIdx[i])) {
                    bestVal[i] = v.y; bestIdx[i] = g0 + 1;
                }
            }
        }
    }

    // cross-thread (over tx) reduction; reuse As/Bs storage
    __syncthreads();
    float* redV = &As[0][0];                // needs 128*16 floats = 2048 (<4224)
    int*   redI = reinterpret_cast<int*>(&Bs[0][0]);
#pragma unroll
    for (int i = 0; i < 8; ++i) {
        int row = (i < 4) ? (ty * 4 + i) : (64 + ty * 4 + (i - 4));
        redV[row * 16 + tx] = bestVal[i];
        redI[row * 16 + tx] = bestIdx[i];
    }
    __syncthreads();
    if (t < BM) {
        float bv = redV[t * 16];
        int   bi = redI[t * 16];
#pragma unroll
        for (int x = 1; x < 16; ++x) {
            float v = redV[t * 16 + x];
            int   ix = redI[t * 16 + x];
            if (v > bv || (v == bv && ix < bi)) { bv = v; bi = ix; }
        }
        g_pmax[(mBase + t) * NCHUNK + chunk] = bv;
        g_pidx[(mBase + t) * NCHUNK + chunk] = bi;
    }
}

// ---------------- kernel 2: reduce 50 partials per token + gather row --------
__global__ void reduce_gather_kernel(const float* __restrict__ table,
                                     float* __restrict__ out) {
    const int m = blockIdx.x;
    const int t = threadIdx.x;              // 128 threads
    __shared__ float sv[64];
    __shared__ int   si[64];
    if (t < 64) {
        sv[t] = __int_as_float(0xff800000);
        si[t] = 0x7fffffff;
    }
    if (t < NCHUNK) {
        sv[t] = g_pmax[m * NCHUNK + t];
        si[t] = g_pidx[m * NCHUNK + t];
    }
    __syncthreads();
#pragma unroll
    for (int s = 32; s > 0; s >>= 1) {
        if (t < s) {
            float v = sv[t + s];
            int   ix = si[t + s];
            if (v > sv[t] || (v == sv[t] && ix < si[t])) { sv[t] = v; si[t] = ix; }
        }
        __syncthreads();
    }
    const int idx = si[0];
    const float4* src = reinterpret_cast<const float4*>(table + (size_t)idx * K_DIM);
    float4*       dst = reinterpret_cast<float4*>(out + (size_t)m * K_DIM);
#pragma unroll
    for (int f = t; f < K_DIM / 4; f += 128) dst[f] = src[f];
}

// ---------------- launch ------------------------------------------------------
extern "C" void kernel_launch(void* const* d_in, const int* in_sizes, int n_in,
                              void* d_out, int out_size) {
    // Identify the table by element count (embeds/noise are interchangeable:
    // perturb is a commutative add).
    const float* table = nullptr;
    const float* a = nullptr;
    const float* b = nullptr;
    for (int i = 0; i < 3; ++i) {
        const float* p = reinterpret_cast<const float*>(d_in[i]);
        if (in_sizes[i] == V_TOT * K_DIM) table = p;
        else if (!a) a = p;
        else b = p;
    }
    float* out = reinterpret_cast<float*>(d_out);

    perturb_kernel<<<M_TOT * K_DIM / 4 / NTHREADS, NTHREADS>>>(a, b);
    dim3 grid(M_TOT / BM, NCHUNK);           // m-block fastest -> table L2 reuse
    gemm_argmax_kernel<<<grid, NTHREADS>>>(table);
    reduce_gather_kernel<<<M_TOT, 128>>>(table, out);
}

// round 12
// speedup vs baseline: 5.8494x; 5.8494x over previous
#include <cuda_runtime.h>
#include <cuda_bf16.h>
#include <cstdint>

// Problem shape: B=2,S=2048 -> M=4096 tokens, D=K=1024, V=32000
#define M_TOT 4096
#define K_DIM 1024
#define V_TOT 32000

#define BM 128
#define BN 128
#define BK 32                      // bf16 elems per k-tile (64 B rows)
#define STAGES 4
#define NKT (K_DIM / BK)           // 32 k-iterations
#define NSUB (V_TOT / 16)          // 2000 16-vocab sub-blocks per token
#define MARGIN 1.25f

#define STAGE_BYTES 16384          // A 8KB + B 8KB
#define SMEM_GEMM_BYTES (STAGES * STAGE_BYTES)   // 64 KB

// ---------------- device scratch (allocation-free rule) ----------------------
__device__ float          g_perturbed[M_TOT * K_DIM];                 // 16.8 MB
__device__ __nv_bfloat16  g_Abf16[M_TOT * K_DIM];                     // 8.4 MB
__device__ __nv_bfloat16  g_Tbf16[(size_t)V_TOT * K_DIM];             // 65.5 MB
__device__ uint2          g_pack[(size_t)M_TOT * NSUB];               // 65.5 MB

// ---------------- PTX helpers (ALL baseline sm_80/90 features) ---------------
__device__ __forceinline__ uint32_t smem_u32(const void* p) {
    uint32_t a;
    asm("{ .reg .u64 t; cvta.to.shared.u64 t, %1; cvt.u32.u64 %0, t; }"
        : "=r"(a) : "l"(p));
    return a;
}
__device__ __forceinline__ void cp_async16(uint32_t s, const void* g) {
    asm volatile("cp.async.cg.shared.global [%0], [%1], 16;"
                 :: "r"(s), "l"(g) : "memory");
}
#define CP_COMMIT() asm volatile("cp.async.commit_group;" ::: "memory")
#define CP_WAIT(n)  asm volatile("cp.async.wait_group %0;" :: "n"(n) : "memory")

__device__ __forceinline__ void ldsm_x4(uint32_t& r0, uint32_t& r1,
                                        uint32_t& r2, uint32_t& r3, uint32_t a) {
    asm volatile("ldmatrix.sync.aligned.m8n8.x4.shared.b16 {%0,%1,%2,%3}, [%4];"
                 : "=r"(r0), "=r"(r1), "=r"(r2), "=r"(r3) : "r"(a));
}
__device__ __forceinline__ void ldsm_x2(uint32_t& r0, uint32_t& r1, uint32_t a) {
    asm volatile("ldmatrix.sync.aligned.m8n8.x2.shared.b16 {%0,%1}, [%2];"
                 : "=r"(r0), "=r"(r1) : "r"(a));
}
__device__ __forceinline__ void mma_bf16(float* d, const uint32_t* a,
                                         const uint32_t* b) {
    asm volatile(
        "mma.sync.aligned.m16n8k16.row.col.f32.bf16.bf16.f32 "
        "{%0,%1,%2,%3}, {%4,%5,%6,%7}, {%8,%9}, {%0,%1,%2,%3};"
        : "+f"(d[0]), "+f"(d[1]), "+f"(d[2]), "+f"(d[3])
        : "r"(a[0]), "r"(a[1]), "r"(a[2]), "r"(a[3]), "r"(b[0]), "r"(b[1]));
}
// smem tile byte offset: 64B rows, chunk-XOR swizzle (conflict-free for
// 16B cp.async writes and ldmatrix 8-lane phases)
__device__ __forceinline__ uint32_t swz(int row, int ch) {
    return (uint32_t)(row * 64 + ((ch ^ ((row >> 1) & 3)) << 4));
}

// ---------------- kernel 0: perturbed = embeds + noise (fp32 + bf16) ---------
__global__ void perturb_kernel(const float* __restrict__ e,
                               const float* __restrict__ n) {
    int i = blockIdx.x * blockDim.x + threadIdx.x;
    float4 a = reinterpret_cast<const float4*>(e)[i];
    float4 b = reinterpret_cast<const float4*>(n)[i];
    a.x += b.x; a.y += b.y; a.z += b.z; a.w += b.w;
    reinterpret_cast<float4*>(g_perturbed)[i] = a;
    __nv_bfloat162 lo = __float22bfloat162_rn(make_float2(a.x, a.y));
    __nv_bfloat162 hi = __float22bfloat162_rn(make_float2(a.z, a.w));
    uint2 p;
    p.x = *reinterpret_cast<uint32_t*>(&lo);
    p.y = *reinterpret_cast<uint32_t*>(&hi);
    reinterpret_cast<uint2*>(g_Abf16)[i] = p;
}

// ---------------- kernel 1: table fp32 -> bf16 --------------------------------
__global__ void convert_table_kernel(const float* __restrict__ tbl) {
    int i = blockIdx.x * blockDim.x + threadIdx.x;
    float4 a = reinterpret_cast<const float4*>(tbl)[i];
    __nv_bfloat162 lo = __float22bfloat162_rn(make_float2(a.x, a.y));
    __nv_bfloat162 hi = __float22bfloat162_rn(make_float2(a.z, a.w));
    uint2 p;
    p.x = *reinterpret_cast<uint32_t*>(&lo);
    p.y = *reinterpret_cast<uint32_t*>(&hi);
    reinterpret_cast<uint2*>(g_Tbf16)[i] = p;
}

// ---------------- kernel 2: bf16 mma.sync GEMM + per-16 sub-block max ---------
// grid (32 m-tiles [fast], 250 n-tiles), 256 threads, warp grid 2x4 (64x32/warp)
__global__ __launch_bounds__(256)
void gemm_kernel() {
    extern __shared__ char dsmem[];
    const uint32_t sb = smem_u32(dsmem);
    const int t = threadIdx.x, lane = t & 31, wid = t >> 5;
    const int wm = wid >> 2;                 // 0..1
    const int wn = wid & 3;                  // 0..3
    const int mBase = blockIdx.x * BM;
    const int nBase = blockIdx.y * BN;

    // ---- cp.async source/dest (2 chunks of A + 2 of B per thread per stage)
    const int lrow = t >> 2, lch = t & 3;    // 128 rows x 4 chunks, threads 0..255 -> first half
    const __nv_bfloat16* gA0 = g_Abf16 + (size_t)(mBase + lrow) * K_DIM + lch * 8;
    const __nv_bfloat16* gA1 = gA0 + (size_t)64 * K_DIM;
    const __nv_bfloat16* gB0 = g_Tbf16 + (size_t)(nBase + lrow) * K_DIM + lch * 8;
    const __nv_bfloat16* gB1 = gB0 + (size_t)64 * K_DIM;
    const uint32_t sA0 = swz(lrow, lch), sA1 = swz(lrow + 64, lch);

    // ---- ldmatrix lane addresses
    // A (x4): rows wm*64 + mf*16 + (lane&15), chunk ks*2 + (lane>>4)
    const int arow = wm * 64 + (lane & 15);
    const int achq = lane >> 4;
    // B (x2): rows wn*32 + nf*8 + (lane&7), chunk ks*2 + ((lane>>3)&1)
    const int brow = wn * 32 + ((lane & 15) & 7);
    const int bchq = ((lane & 15) >> 3) & 1;

    uint32_t aAddr[2], bAddr[2];
#pragma unroll
    for (int ks = 0; ks < 2; ++ks) {
        aAddr[ks] = swz(arow, ks * 2 + achq);
        bAddr[ks] = 8192u + swz(brow, ks * 2 + bchq);
    }

    float acc[4][4][4];
#pragma unroll
    for (int i = 0; i < 4; ++i)
#pragma unroll
        for (int j = 0; j < 4; ++j)
#pragma unroll
            for (int r = 0; r < 4; ++r) acc[i][j][r] = 0.f;

    // ---- prologue: fill first STAGES-1 stages
#pragma unroll
    for (int kt = 0; kt < STAGES - 1; ++kt) {
        const uint32_t st = sb + kt * STAGE_BYTES;
        cp_async16(st + sA0, gA0 + kt * BK);
        cp_async16(st + sA1, gA1 + kt * BK);
        cp_async16(st + 8192u + sA0, gB0 + kt * BK);
        cp_async16(st + 8192u + sA1, gB1 + kt * BK);
        CP_COMMIT();
    }

    // ---- main loop
    for (int kt = 0; kt < NKT; ++kt) {
        CP_WAIT(STAGES - 2);
        __syncthreads();
        // prefetch stage kt+STAGES-1
        if (kt + STAGES - 1 < NKT) {
            const int pf = kt + STAGES - 1;
            const uint32_t st = sb + (pf & (STAGES - 1)) * STAGE_BYTES;
            cp_async16(st + sA0, gA0 + pf * BK);
            cp_async16(st + sA1, gA1 + pf * BK);
            cp_async16(st + 8192u + sA0, gB0 + pf * BK);
            cp_async16(st + 8192u + sA1, gB1 + pf * BK);
        }
        CP_COMMIT();

        const uint32_t st = sb + (kt & (STAGES - 1)) * STAGE_BYTES;
#pragma unroll
        for (int ks = 0; ks < 2; ++ks) {
            uint32_t af[4][4], bf[4][2];
#pragma unroll
            for (int mf = 0; mf < 4; ++mf)
                ldsm_x4(af[mf][0], af[mf][1], af[mf][2], af[mf][3],
                        st + aAddr[ks] + mf * 1024u);
#pragma unroll
            for (int nf = 0; nf < 4; ++nf)
                ldsm_x2(bf[nf][0], bf[nf][1], st + bAddr[ks] + nf * 512u);
#pragma unroll
            for (int mf = 0; mf < 4; ++mf)
#pragma unroll
                for (int nf = 0; nf < 4; ++nf)
                    mma_bf16(acc[mf][nf], af[mf], bf[nf]);
        }
    }

    // ---- epilogue: per-token per-16-col (max, argmax)
    CP_WAIT(0);
    __syncthreads();                         // done with tiles; reuse smem
    uint2* stage = reinterpret_cast<uint2*>(dsmem);   // 128 rows x 8 subs = 8KB
    const int q = lane & 3, rq = lane >> 2;

#pragma unroll
    for (int mf = 0; mf < 4; ++mf) {
#pragma unroll
        for (int half = 0; half < 2; ++half) {
            const int row = wm * 64 + mf * 16 + half * 8 + rq;
#pragma unroll
            for (int b = 0; b < 2; ++b) {
                // 4 candidate cols this thread owns in 16-block b:
                //   nf=2b  -> cols 2q, 2q+1 ; nf=2b+1 -> cols 8+2q, 9+2q
                float bv = acc[mf][2 * b][half * 2];
                int   bc = 2 * q;
                float v1 = acc[mf][2 * b][half * 2 + 1];
                if (v1 > bv) { bv = v1; bc = 2 * q + 1; }
                float v2 = acc[mf][2 * b + 1][half * 2];
                if (v2 > bv || (v2 == bv && 8 + 2 * q < bc)) { bv = v2; bc = 8 + 2 * q; }
                float v3 = acc[mf][2 * b + 1][half * 2 + 1];
                if (v3 > bv || (v3 == bv && 9 + 2 * q < bc)) { bv = v3; bc = 9 + 2 * q; }
                int bi = nBase + wn * 32 + b * 16 + bc;
#pragma unroll
                for (int o = 1; o <= 2; o <<= 1) {
                    float ov = __shfl_xor_sync(0xffffffffu, bv, o);
                    int   oi = __shfl_xor_sync(0xffffffffu, bi, o);
                    if (ov > bv || (ov == bv && oi < bi)) { bv = ov; bi = oi; }
                }
                if (q == 0)
                    stage[row * 8 + wn * 2 + b] =
                        make_uint2(__float_as_uint(bv), (uint32_t)bi);
            }
        }
    }
    __syncthreads();
    const int subBase = nBase / 16;
#pragma unroll
    for (int i = 0; i < 4; ++i) {            // 1024 entries, coalesced 64B rows
        int p = t + i * 256;
        int row = p >> 3, s = p & 7;
        g_pack[(size_t)(mBase + row) * NSUB + subBase + s] = stage[p];
    }
}

// ---------------- kernel 3: fp32 rescore of candidate sub-blocks + gather ----
__global__ __launch_bounds__(256)
void rescore_kernel(const float* __restrict__ table, float* __restrict__ out) {
    const int m = blockIdx.x, t = threadIdx.x;
    __shared__ float sA[K_DIM];
    __shared__ float red[256];
    __shared__ int   redi[256];
    __shared__ int   cand[256];
    __shared__ int   ncand;

    for (int i = t; i < K_DIM / 4; i += 256)
        reinterpret_cast<float4*>(sA)[i] =
            reinterpret_cast<const float4*>(g_perturbed + (size_t)m * K_DIM)[i];

    const uint2* pk = g_pack + (size_t)m * NSUB;
    float lm = __int_as_float(0xff800000);
    for (int i = t; i < NSUB; i += 256)
        lm = fmaxf(lm, __uint_as_float(pk[i].x));
    red[t] = lm;
    __syncthreads();
    for (int s = 128; s; s >>= 1) {
        if (t < s) red[t] = fmaxf(red[t], red[t + s]);
        __syncthreads();
    }
    const float gmax = red[0];
    if (t == 0) ncand = 0;
    __syncthreads();
    for (int i = t; i < NSUB; i += 256)
        if (__uint_as_float(pk[i].x) >= gmax - MARGIN) {
            int p = atomicAdd(&ncand, 1);
            if (p < 256) cand[p] = i;
        }
    __syncthreads();
    const int nc = min(ncand, 256);

    float bv = __int_as_float(0xff800000);
    int bi = 0x7fffffff;
    const int wid = t >> 5, lane = t & 31;
    for (int c = 0; c < nc; ++c) {
        const int sbk = cand[c];
#pragma unroll
        for (int r = 0; r < 2; ++r) {        // 8 warps x 2 rows = 16 rows
            const int v = sbk * 16 + wid * 2 + r;
            const float* row = table + (size_t)v * K_DIM;
            float s = 0.f;
            for (int j = lane; j < K_DIM; j += 32) s = fmaf(sA[j], __ldg(row + j), s);
#pragma unroll
            for (int o = 16; o; o >>= 1) s += __shfl_xor_sync(0xffffffffu, s, o);
            if (lane == 0) {
                if (s > bv || (s == bv && v < bi)) { bv = s; bi = v; }
            }
        }
    }
    red[t] = bv; redi[t] = bi;
    __syncthreads();
    for (int s2 = 128; s2; s2 >>= 1) {
        if (t < s2) {
            float v = red[t + s2]; int ix = redi[t + s2];
            if (v > red[t] || (v == red[t] && ix < redi[t])) { red[t] = v; redi[t] = ix; }
        }
        __syncthreads();
    }
    const int idx = redi[0];
    const float4* src = reinterpret_cast<const float4*>(table + (size_t)idx * K_DIM);
    float4*       dst = reinterpret_cast<float4*>(out + (size_t)m * K_DIM);
    for (int f = t; f < K_DIM / 4; f += 256) dst[f] = src[f];
}

// ---------------- launch ------------------------------------------------------
extern "C" void kernel_launch(void* const* d_in, const int* in_sizes, int n_in,
                              void* d_out, int out_size) {
    const float* table = nullptr;
    const float* a = nullptr;
    const float* b = nullptr;
    for (int i = 0; i < 3; ++i) {
        const float* p = reinterpret_cast<const float*>(d_in[i]);
        if (in_sizes[i] == V_TOT * K_DIM) table = p;
        else if (!a) a = p;
        else b = p;
    }
    float* out = reinterpret_cast<float*>(d_out);

    cudaFuncSetAttribute(gemm_kernel,
                         cudaFuncAttributeMaxDynamicSharedMemorySize,
                         SMEM_GEMM_BYTES);

    perturb_kernel<<<M_TOT * K_DIM / 4 / 256, 256>>>(a, b);
    convert_table_kernel<<<V_TOT * K_DIM / 4 / 256, 256>>>(table);
    dim3 grid(M_TOT / BM, V_TOT / BN);       // m fastest -> table L2 reuse
    gemm_kernel<<<grid, 256, SMEM_GEMM_BYTES>>>();
    rescore_kernel<<<M_TOT, 256>>>(table, out);
}

// round 13
// speedup vs baseline: 5.8498x; 1.0001x over previous
#include <cuda_runtime.h>
#include <cuda_bf16.h>
#include <cstdint>

// Problem shape: B=2,S=2048 -> M=4096 tokens, D=K=1024, V=32000
#define M_TOT 4096
#define K_DIM 1024
#define V_TOT 32000

#define BM 128
#define BN 128
#define BK 32                      // bf16 elems per k-tile (64 B rows)
#define STAGES 4
#define NKT (K_DIM / BK)           // 32 k-iterations
#define NSUB (V_TOT / 16)          // 2000 16-vocab sub-blocks per token
#define MARGIN 1.25f

#define STAGE_BYTES 16384          // A 8KB + B 8KB
#define SMEM_GEMM_BYTES (STAGES * STAGE_BYTES)   // 64 KB

// ---------------- device scratch (allocation-free rule) ----------------------
__device__ float          g_perturbed[M_TOT * K_DIM];                 // 16.8 MB
__device__ __nv_bfloat16  g_Abf16[M_TOT * K_DIM];                     // 8.4 MB
__device__ __nv_bfloat16  g_Tbf16[(size_t)V_TOT * K_DIM];             // 65.5 MB
__device__ uint2          g_pack[(size_t)M_TOT * NSUB];               // 65.5 MB

// ---------------- PTX helpers (ALL baseline sm_80/90 features) ---------------
__device__ __forceinline__ uint32_t smem_u32(const void* p) {
    uint32_t a;
    asm("{ .reg .u64 t; cvta.to.shared.u64 t, %1; cvt.u32.u64 %0, t; }"
        : "=r"(a) : "l"(p));
    return a;
}
__device__ __forceinline__ void cp_async16(uint32_t s, const void* g) {
    asm volatile("cp.async.cg.shared.global [%0], [%1], 16;"
                 :: "r"(s), "l"(g) : "memory");
}
#define CP_COMMIT() asm volatile("cp.async.commit_group;" ::: "memory")
#define CP_WAIT(n)  asm volatile("cp.async.wait_group %0;" :: "n"(n) : "memory")

__device__ __forceinline__ void ldsm_x4(uint32_t& r0, uint32_t& r1,
                                        uint32_t& r2, uint32_t& r3, uint32_t a) {
    asm volatile("ldmatrix.sync.aligned.m8n8.x4.shared.b16 {%0,%1,%2,%3}, [%4];"
                 : "=r"(r0), "=r"(r1), "=r"(r2), "=r"(r3) : "r"(a));
}
__device__ __forceinline__ void ldsm_x2(uint32_t& r0, uint32_t& r1, uint32_t a) {
    asm volatile("ldmatrix.sync.aligned.m8n8.x2.shared.b16 {%0,%1}, [%2];"
                 : "=r"(r0), "=r"(r1) : "r"(a));
}
__device__ __forceinline__ void mma_bf16(float* d, const uint32_t* a,
                                         const uint32_t* b) {
    asm volatile(
        "mma.sync.aligned.m16n8k16.row.col.f32.bf16.bf16.f32 "
        "{%0,%1,%2,%3}, {%4,%5,%6,%7}, {%8,%9}, {%0,%1,%2,%3};"
        : "+f"(d[0]), "+f"(d[1]), "+f"(d[2]), "+f"(d[3])
        : "r"(a[0]), "r"(a[1]), "r"(a[2]), "r"(a[3]), "r"(b[0]), "r"(b[1]));
}
// smem tile byte offset: 64B rows, chunk-XOR swizzle (conflict-free for
// 16B cp.async writes and ldmatrix 8-lane phases)
__device__ __forceinline__ uint32_t swz(int row, int ch) {
    return (uint32_t)(row * 64 + ((ch ^ ((row >> 1) & 3)) << 4));
}

// ---------------- kernel 0: perturbed = embeds + noise (fp32 + bf16) ---------
__global__ void perturb_kernel(const float* __restrict__ e,
                               const float* __restrict__ n) {
    int i = blockIdx.x * blockDim.x + threadIdx.x;
    float4 a = reinterpret_cast<const float4*>(e)[i];
    float4 b = reinterpret_cast<const float4*>(n)[i];
    a.x += b.x; a.y += b.y; a.z += b.z; a.w += b.w;
    reinterpret_cast<float4*>(g_perturbed)[i] = a;
    __nv_bfloat162 lo = __float22bfloat162_rn(make_float2(a.x, a.y));
    __nv_bfloat162 hi = __float22bfloat162_rn(make_float2(a.z, a.w));
    uint2 p;
    p.x = *reinterpret_cast<uint32_t*>(&lo);
    p.y = *reinterpret_cast<uint32_t*>(&hi);
    reinterpret_cast<uint2*>(g_Abf16)[i] = p;
}

// ---------------- kernel 1: table fp32 -> bf16 --------------------------------
__global__ void convert_table_kernel(const float* __restrict__ tbl) {
    int i = blockIdx.x * blockDim.x + threadIdx.x;
    float4 a = reinterpret_cast<const float4*>(tbl)[i];
    __nv_bfloat162 lo = __float22bfloat162_rn(make_float2(a.x, a.y));
    __nv_bfloat162 hi = __float22bfloat162_rn(make_float2(a.z, a.w));
    uint2 p;
    p.x = *reinterpret_cast<uint32_t*>(&lo);
    p.y = *reinterpret_cast<uint32_t*>(&hi);
    reinterpret_cast<uint2*>(g_Tbf16)[i] = p;
}

// ---------------- kernel 2: bf16 mma.sync GEMM + per-16 sub-block max ---------
// grid (32 m-tiles [fast], 250 n-tiles), 256 threads, warp grid 2x4 (64x32/warp)
__global__ __launch_bounds__(256)
void gemm_kernel() {
    extern __shared__ char dsmem[];
    const uint32_t sb = smem_u32(dsmem);
    const int t = threadIdx.x, lane = t & 31, wid = t >> 5;
    const int wm = wid >> 2;                 // 0..1
    const int wn = wid & 3;                  // 0..3
    const int mBase = blockIdx.x * BM;
    const int nBase = blockIdx.y * BN;

    // ---- cp.async source/dest (2 chunks of A + 2 of B per thread per stage)
    const int lrow = t >> 2, lch = t & 3;    // 128 rows x 4 chunks, threads 0..255 -> first half
    const __nv_bfloat16* gA0 = g_Abf16 + (size_t)(mBase + lrow) * K_DIM + lch * 8;
    const __nv_bfloat16* gA1 = gA0 + (size_t)64 * K_DIM;
    const __nv_bfloat16* gB0 = g_Tbf16 + (size_t)(nBase + lrow) * K_DIM + lch * 8;
    const __nv_bfloat16* gB1 = gB0 + (size_t)64 * K_DIM;
    const uint32_t sA0 = swz(lrow, lch), sA1 = swz(lrow + 64, lch);

    // ---- ldmatrix lane addresses
    // A (x4): rows wm*64 + mf*16 + (lane&15), chunk ks*2 + (lane>>4)
    const int arow = wm * 64 + (lane & 15);
    const int achq = lane >> 4;
    // B (x2): rows wn*32 + nf*8 + (lane&7), chunk ks*2 + ((lane>>3)&1)
    const int brow = wn * 32 + ((lane & 15) & 7);
    const int bchq = ((lane & 15) >> 3) & 1;

    uint32_t aAddr[2], bAddr[2];
#pragma unroll
    for (int ks = 0; ks < 2; ++ks) {
        aAddr[ks] = swz(arow, ks * 2 + achq);
        bAddr[ks] = 8192u + swz(brow, ks * 2 + bchq);
    }

    float acc[4][4][4];
#pragma unroll
    for (int i = 0; i < 4; ++i)
#pragma unroll
        for (int j = 0; j < 4; ++j)
#pragma unroll
            for (int r = 0; r < 4; ++r) acc[i][j][r] = 0.f;

    // ---- prologue: fill first STAGES-1 stages
#pragma unroll
    for (int kt = 0; kt < STAGES - 1; ++kt) {
        const uint32_t st = sb + kt * STAGE_BYTES;
        cp_async16(st + sA0, gA0 + kt * BK);
        cp_async16(st + sA1, gA1 + kt * BK);
        cp_async16(st + 8192u + sA0, gB0 + kt * BK);
        cp_async16(st + 8192u + sA1, gB1 + kt * BK);
        CP_COMMIT();
    }

    // ---- main loop
    for (int kt = 0; kt < NKT; ++kt) {
        CP_WAIT(STAGES - 2);
        __syncthreads();
        // prefetch stage kt+STAGES-1
        if (kt + STAGES - 1 < NKT) {
            const int pf = kt + STAGES - 1;
            const uint32_t st = sb + (pf & (STAGES - 1)) * STAGE_BYTES;
            cp_async16(st + sA0, gA0 + pf * BK);
            cp_async16(st + sA1, gA1 + pf * BK);
            cp_async16(st + 8192u + sA0, gB0 + pf * BK);
            cp_async16(st + 8192u + sA1, gB1 + pf * BK);
        }
        CP_COMMIT();

        const uint32_t st = sb + (kt & (STAGES - 1)) * STAGE_BYTES;
#pragma unroll
        for (int ks = 0; ks < 2; ++ks) {
            uint32_t af[4][4], bf[4][2];
#pragma unroll
            for (int mf = 0; mf < 4; ++mf)
                ldsm_x4(af[mf][0], af[mf][1], af[mf][2], af[mf][3],
                        st + aAddr[ks] + mf * 1024u);
#pragma unroll
            for (int nf = 0; nf < 4; ++nf)
                ldsm_x2(bf[nf][0], bf[nf][1], st + bAddr[ks] + nf * 512u);
#pragma unroll
            for (int mf = 0; mf < 4; ++mf)
#pragma unroll
                for (int nf = 0; nf < 4; ++nf)
                    mma_bf16(acc[mf][nf], af[mf], bf[nf]);
        }
    }

    // ---- epilogue: per-token per-16-col (max, argmax)
    CP_WAIT(0);
    __syncthreads();                         // done with tiles; reuse smem
    uint2* stage = reinterpret_cast<uint2*>(dsmem);   // 128 rows x 8 subs = 8KB
    const int q = lane & 3, rq = lane >> 2;

#pragma unroll
    for (int mf = 0; mf < 4; ++mf) {
#pragma unroll
        for (int half = 0; half < 2; ++half) {
            const int row = wm * 64 + mf * 16 + half * 8 + rq;
#pragma unroll
            for (int b = 0; b < 2; ++b) {
                // 4 candidate cols this thread owns in 16-block b:
                //   nf=2b  -> cols 2q, 2q+1 ; nf=2b+1 -> cols 8+2q, 9+2q
                float bv = acc[mf][2 * b][half * 2];
                int   bc = 2 * q;
                float v1 = acc[mf][2 * b][half * 2 + 1];
                if (v1 > bv) { bv = v1; bc = 2 * q + 1; }
                float v2 = acc[mf][2 * b + 1][half * 2];
                if (v2 > bv || (v2 == bv && 8 + 2 * q < bc)) { bv = v2; bc = 8 + 2 * q; }
                float v3 = acc[mf][2 * b + 1][half * 2 + 1];
                if (v3 > bv || (v3 == bv && 9 + 2 * q < bc)) { bv = v3; bc = 9 + 2 * q; }
                int bi = nBase + wn * 32 + b * 16 + bc;
#pragma unroll
                for (int o = 1; o <= 2; o <<= 1) {
                    float ov = __shfl_xor_sync(0xffffffffu, bv, o);
                    int   oi = __shfl_xor_sync(0xffffffffu, bi, o);
                    if (ov > bv || (ov == bv && oi < bi)) { bv = ov; bi = oi; }
                }
                if (q == 0)
                    stage[row * 8 + wn * 2 + b] =
                        make_uint2(__float_as_uint(bv), (uint32_t)bi);
            }
        }
    }
    __syncthreads();
    const int subBase = nBase / 16;
#pragma unroll
    for (int i = 0; i < 4; ++i) {            // 1024 entries, coalesced 64B rows
        int p = t + i * 256;
        int row = p >> 3, s = p & 7;
        g_pack[(size_t)(mBase + row) * NSUB + subBase + s] = stage[p];
    }
}

// ---------------- kernel 3: fp32 rescore of candidate sub-blocks + gather ----
__global__ __launch_bounds__(256)
void rescore_kernel(const float* __restrict__ table, float* __restrict__ out) {
    const int m = blockIdx.x, t = threadIdx.x;
    __shared__ float sA[K_DIM];
    __shared__ float red[256];
    __shared__ int   redi[256];
    __shared__ int   cand[256];
    __shared__ int   ncand;

    for (int i = t; i < K_DIM / 4; i += 256)
        reinterpret_cast<float4*>(sA)[i] =
            reinterpret_cast<const float4*>(g_perturbed + (size_t)m * K_DIM)[i];

    const uint2* pk = g_pack + (size_t)m * NSUB;
    float lm = __int_as_float(0xff800000);
    for (int i = t; i < NSUB; i += 256)
        lm = fmaxf(lm, __uint_as_float(pk[i].x));
    red[t] = lm;
    __syncthreads();
    for (int s = 128; s; s >>= 1) {
        if (t < s) red[t] = fmaxf(red[t], red[t + s]);
        __syncthreads();
    }
    const float gmax = red[0];
    if (t == 0) ncand = 0;
    __syncthreads();
    for (int i = t; i < NSUB; i += 256)
        if (__uint_as_float(pk[i].x) >= gmax - MARGIN) {
            int p = atomicAdd(&ncand, 1);
            if (p < 256) cand[p] = i;
        }
    __syncthreads();
    const int nc = min(ncand, 256);

    float bv = __int_as_float(0xff800000);
    int bi = 0x7fffffff;
    const int wid = t >> 5, lane = t & 31;
    for (int c = 0; c < nc; ++c) {
        const int sbk = cand[c];
#pragma unroll
        for (int r = 0; r < 2; ++r) {        // 8 warps x 2 rows = 16 rows
            const int v = sbk * 16 + wid * 2 + r;
            const float* row = table + (size_t)v * K_DIM;
            float s = 0.f;
            for (int j = lane; j < K_DIM; j += 32) s = fmaf(sA[j], __ldg(row + j), s);
#pragma unroll
            for (int o = 16; o; o >>= 1) s += __shfl_xor_sync(0xffffffffu, s, o);
            if (lane == 0) {
                if (s > bv || (s == bv && v < bi)) { bv = s; bi = v; }
            }
        }
    }
    red[t] = bv; redi[t] = bi;
    __syncthreads();
    for (int s2 = 128; s2; s2 >>= 1) {
        if (t < s2) {
            float v = red[t + s2]; int ix = redi[t + s2];
            if (v > red[t] || (v == red[t] && ix < redi[t])) { red[t] = v; redi[t] = ix; }
        }
        __syncthreads();
    }
    const int idx = redi[0];
    const float4* src = reinterpret_cast<const float4*>(table + (size_t)idx * K_DIM);
    float4*       dst = reinterpret_cast<float4*>(out + (size_t)m * K_DIM);
    for (int f = t; f < K_DIM / 4; f += 256) dst[f] = src[f];
}

// ---------------- launch ------------------------------------------------------
extern "C" void kernel_launch(void* const* d_in, const int* in_sizes, int n_in,
                              void* d_out, int out_size) {
    const float* table = nullptr;
    const float* a = nullptr;
    const float* b = nullptr;
    for (int i = 0; i < 3; ++i) {
        const float* p = reinterpret_cast<const float*>(d_in[i]);
        if (in_sizes[i] == V_TOT * K_DIM) table = p;
        else if (!a) a = p;
        else b = p;
    }
    float* out = reinterpret_cast<float*>(d_out);

    cudaFuncSetAttribute(gemm_kernel,
                         cudaFuncAttributeMaxDynamicSharedMemorySize,
                         SMEM_GEMM_BYTES);

    perturb_kernel<<<M_TOT * K_DIM / 4 / 256, 256>>>(a, b);
    convert_table_kernel<<<V_TOT * K_DIM / 4 / 256, 256>>>(table);
    dim3 grid(M_TOT / BM, V_TOT / BN);       // m fastest -> table L2 reuse
    gemm_kernel<<<grid, 256, SMEM_GEMM_BYTES>>>();
    rescore_kernel<<<M_TOT, 256>>>(table, out);
}